// round 14
// baseline (speedup 1.0000x reference)
#include <cuda_runtime.h>
#include <cuda_bf16.h>

#define NN 50000
#define EE 800000
#define ET (EE + NN)          // edges + self loops = 850000
#define HC 128                // H*C
#define HH 4
#define CC 32
#define NB 49                 // scan blocks: ceil(NN/1024)
#define GRID1 ((NN + 127) / 128)

// ---------------- device scratch (static, no allocation) ----------------
__device__ float g_xp1[NN * HC];     // layer1 linear out (full)
__device__ float g_xp2[NN * HC];     // layer2 linear out (COMPACTED)
__device__ float g_as [NN * HH];     // layer-1 alpha_src (full node idx)
__device__ float g_ad [NN * HH];     // layer-1 alpha_dst
__device__ float g_as2[NN * HH];     // layer-2 alpha_src (compact idx)
__device__ float g_ad2[NN * HH];     // layer-2 alpha_dst
__device__ int   g_cnt[NN];          // degree histogram / scatter countdown
__device__ int   g_rowptr[NN + 1];
__device__ int   g_srcs[ET];         // CSR (by dst) source indices
__device__ int   g_mark[NN];
__device__ int   g_finv[NN];         // node -> compact frontier index
__device__ int   g_flist[NN];        // compact frontier index -> node
__device__ int   g_fcnt;
__device__ int   g_bsum[NB];

// ---------------- f32x2 helpers ----------------
#define FMA2(acc, a, b) asm("fma.rn.f32x2 %0, %1, %2, %0;" : "+l"(acc) : "l"(a), "l"(b))
#define SPLAT2(dst, s)  asm("mov.b64 %0, {%1, %1};" : "=l"(dst) : "r"(__float_as_uint(s)))
#define UNPACK2(lo, hi, p) asm("mov.b64 {%0, %1}, %2;" : "=r"(lo), "=r"(hi) : "l"(p))

// ---------------- init: zero cnt/mark/fcnt ----------------
__global__ void init_kernel() {
    int i = blockIdx.x * blockDim.x + threadIdx.x;
    if (i < NN) { g_cnt[i] = 0; g_mark[i] = 0; }
    if (i == 0) g_fcnt = 0;
}

__global__ void hist_kernel(const int* __restrict__ ei) {
    int e = blockIdx.x * blockDim.x + threadIdx.x;
    if (e >= ET) return;
    int d = (e < EE) ? ei[EE + e] : (e - EE);
    atomicAdd(&g_cnt[d], 1);
}

// ---------------- 2-phase scan ----------------
__global__ void scan1_kernel() {
    __shared__ int wsum[32];
    int tid = threadIdx.x, lane = tid & 31, w = tid >> 5;
    int i = blockIdx.x * 1024 + tid;
    int v = (i < NN) ? g_cnt[i] : 0;
    int x = v;
    #pragma unroll
    for (int o = 1; o < 32; o <<= 1) {
        int t = __shfl_up_sync(0xffffffffu, x, o);
        if (lane >= o) x += t;
    }
    if (lane == 31) wsum[w] = x;
    __syncthreads();
    if (w == 0) {
        int y = wsum[lane];
        #pragma unroll
        for (int o = 1; o < 32; o <<= 1) {
            int t = __shfl_up_sync(0xffffffffu, y, o);
            if (lane >= o) y += t;
        }
        wsum[lane] = y;
    }
    __syncthreads();
    int incl = x + (w > 0 ? wsum[w - 1] : 0);
    if (i < NN) g_rowptr[i + 1] = incl;
    if (tid == 1023) g_bsum[blockIdx.x] = incl;
    if (i == 0) g_rowptr[0] = 0;
}

__global__ void scan3_kernel() {
    __shared__ int s_off;
    int tid = threadIdx.x;
    if (tid < 32) {
        int v = 0;
        if (tid      < (int)blockIdx.x) v += g_bsum[tid];
        if (tid + 32 < (int)blockIdx.x) v += g_bsum[tid + 32];
        #pragma unroll
        for (int o = 16; o; o >>= 1) v += __shfl_xor_sync(0xffffffffu, v, o);
        if (tid == 0) s_off = v;
    }
    __syncthreads();
    int i = blockIdx.x * 1024 + tid;
    if (i < NN && blockIdx.x > 0) g_rowptr[i + 1] += s_off;
}

__global__ void scatter_kernel(const int* __restrict__ ei) {
    int e = blockIdx.x * blockDim.x + threadIdx.x;
    if (e >= ET) return;
    int s, d;
    if (e < EE) { s = ei[e]; d = ei[EE + e]; }
    else        { s = e - EE; d = s; }
    int r = atomicSub(&g_cnt[d], 1);
    g_srcs[g_rowptr[d] + r - 1] = s;
}

// ---------------- frontier ----------------
__global__ void mark_roots_kernel(const int* __restrict__ roots) {
    int r = roots[blockIdx.x];
    if (threadIdx.x == 0) g_mark[r] = 1;
    int beg = g_rowptr[r], end = g_rowptr[r + 1];
    for (int e = beg + threadIdx.x; e < end; e += 32)
        g_mark[g_srcs[e]] = 1;
}

__global__ void compact_kernel() {
    int i = blockIdx.x * blockDim.x + threadIdx.x;
    int lane = threadIdx.x & 31;
    bool active = (i < NN) && g_mark[i];
    unsigned mask = __ballot_sync(0xffffffffu, active);
    if (!mask) return;
    int leader = __ffs(mask) - 1;
    int base = 0;
    if (lane == leader) base = atomicAdd(&g_fcnt, __popc(mask));
    base = __shfl_sync(0xffffffffu, base, leader);
    if (active) {
        int pos = base + __popc(mask & ((1u << lane) - 1u));
        g_flist[pos] = i;
        g_finv[i] = pos;
    }
}

// ---------------- GEMM1 + fused alpha, A-duplicated smem, double-buffered ----
// C[M,128] = A[M,K] * B[K,128]; epilogue produces as/ad = <row_h, att_h>.
// dyn smem: As2[2][16][256] (A duplicated pairs) + Bs[2][16][128].
template <int K>
__global__ __launch_bounds__(256) void gemm_alpha_kernel(
    const float* __restrict__ A, const float* __restrict__ B, float* __restrict__ Cmat,
    const float* __restrict__ a_src, const float* __restrict__ a_dst,
    float* __restrict__ as_out, float* __restrict__ ad_out)
{
    constexpr int NC = K / 16;
    const int M = NN;
    int row0 = blockIdx.x * 128;

    extern __shared__ float dsm[];
    float (*As2)[16][256] = (float (*)[16][256])dsm;            // 8192 floats
    float (*Bs)[16][128]  = (float (*)[16][128])(dsm + 8192);   // 4096 floats

    int tid = threadIdx.x;
    int tx = tid & 15;       // col group: cols tx*8..tx*8+7
    int ty = tid >> 4;       // row group: rows ty*8..ty*8+7

    unsigned long long acc2[8][4];
    #pragma unroll
    for (int i = 0; i < 8; i++)
        #pragma unroll
        for (int j = 0; j < 4; j++) acc2[i][j] = 0ULL;

    int lr = tid >> 1;           // 0..127 row for A load
    int lk = (tid & 1) * 8;      // 0 or 8
    int bk = tid >> 4;           // 0..15 k-row for B load
    int bn = (tid & 15) * 8;     // col

    int grow = row0 + lr;
    bool arow_ok = grow < M;
    const float* Arow = A + (long)grow * K + lk;
    const float* Bp   = B + bk * 128 + bn;

    float4 pa0, pa1, pb0, pb1;
    if (arow_ok) {
        pa0 = *(const float4*)(Arow);
        pa1 = *(const float4*)(Arow + 4);
    } else {
        pa0 = make_float4(0, 0, 0, 0); pa1 = pa0;
    }
    pb0 = *(const float4*)(Bp);
    pb1 = *(const float4*)(Bp + 4);
    {
        float av[8] = {pa0.x, pa0.y, pa0.z, pa0.w, pa1.x, pa1.y, pa1.z, pa1.w};
        #pragma unroll
        for (int j = 0; j < 8; j++)
            *(float2*)&As2[0][lk + j][2 * lr] = make_float2(av[j], av[j]);
        *(float4*)&Bs[0][bk][bn]     = pb0;
        *(float4*)&Bs[0][bk][bn + 4] = pb1;
    }
    __syncthreads();

    int buf = 0;
    #pragma unroll
    for (int c = 0; c < NC; c++) {
        if (c + 1 < NC) {
            if (arow_ok) {
                pa0 = *(const float4*)(Arow + (c + 1) * 16);
                pa1 = *(const float4*)(Arow + (c + 1) * 16 + 4);
            }
            pb0 = *(const float4*)(Bp + (c + 1) * 16 * 128);
            pb1 = *(const float4*)(Bp + (c + 1) * 16 * 128 + 4);
        }

        #pragma unroll
        for (int k = 0; k < 16; k++) {
            ulonglong2 a0 = *(const ulonglong2*)&As2[buf][k][ty * 16];
            ulonglong2 a1 = *(const ulonglong2*)&As2[buf][k][ty * 16 + 4];
            ulonglong2 a2 = *(const ulonglong2*)&As2[buf][k][ty * 16 + 8];
            ulonglong2 a3 = *(const ulonglong2*)&As2[buf][k][ty * 16 + 12];
            ulonglong2 bl = *(const ulonglong2*)&Bs[buf][k][tx * 8];
            ulonglong2 bh = *(const ulonglong2*)&Bs[buf][k][tx * 8 + 4];
            unsigned long long ap[8] = {a0.x, a0.y, a1.x, a1.y, a2.x, a2.y, a3.x, a3.y};
            unsigned long long br2[4] = {bl.x, bl.y, bh.x, bh.y};
            #pragma unroll
            for (int i = 0; i < 8; i++)
                #pragma unroll
                for (int j = 0; j < 4; j++)
                    FMA2(acc2[i][j], ap[i], br2[j]);
        }

        if (c + 1 < NC) {
            int nb = buf ^ 1;
            float av[8] = {pa0.x, pa0.y, pa0.z, pa0.w, pa1.x, pa1.y, pa1.z, pa1.w};
            #pragma unroll
            for (int j = 0; j < 8; j++)
                *(float2*)&As2[nb][lk + j][2 * lr] = make_float2(av[j], av[j]);
            *(float4*)&Bs[nb][bk][bn]     = pb0;
            *(float4*)&Bs[nb][bk][bn + 4] = pb1;
            __syncthreads();
            buf = nb;
        }
    }

    // attention vectors for this thread's 8-col chunk (within head h = tx>>2)
    float4 av0 = *(const float4*)&a_src[tx * 8];
    float4 av1 = *(const float4*)&a_src[tx * 8 + 4];
    float4 dv0 = *(const float4*)&a_dst[tx * 8];
    float4 dv1 = *(const float4*)&a_dst[tx * 8 + 4];
    int lane = tid & 31;
    int h = tx >> 2;

    #pragma unroll
    for (int i = 0; i < 8; i++) {
        float c[8];
        #pragma unroll
        for (int j = 0; j < 4; j++) {
            unsigned int lo, hi;
            UNPACK2(lo, hi, acc2[i][j]);
            c[2 * j]     = __uint_as_float(lo);
            c[2 * j + 1] = __uint_as_float(hi);
        }
        int gr = row0 + ty * 8 + i;
        bool valid = gr < M;
        if (valid) {
            *(float4*)&Cmat[(long)gr * 128 + tx * 8]     = make_float4(c[0], c[1], c[2], c[3]);
            *(float4*)&Cmat[(long)gr * 128 + tx * 8 + 4] = make_float4(c[4], c[5], c[6], c[7]);
        }
        float s1 = c[0]*av0.x + c[1]*av0.y + c[2]*av0.z + c[3]*av0.w
                 + c[4]*av1.x + c[5]*av1.y + c[6]*av1.z + c[7]*av1.w;
        float s2 = c[0]*dv0.x + c[1]*dv0.y + c[2]*dv0.z + c[3]*dv0.w
                 + c[4]*dv1.x + c[5]*dv1.y + c[6]*dv1.z + c[7]*dv1.w;
        s1 += __shfl_xor_sync(0xffffffffu, s1, 1);
        s1 += __shfl_xor_sync(0xffffffffu, s1, 2);
        s2 += __shfl_xor_sync(0xffffffffu, s2, 1);
        s2 += __shfl_xor_sync(0xffffffffu, s2, 2);
        if (valid && (lane & 3) == 0) {
            as_out[gr * HH + h] = s1;
            ad_out[gr * HH + h] = s2;
        }
    }
}

// ---------------- two-pass softmax aggregation core (slot-parameterized) ----
__device__ __forceinline__ void aggregate_node(
    const float* __restrict__ xp, const float* __restrict__ as_in, float adv,
    int beg, int end, int h, int lane, const int* __restrict__ remap,
    float* __restrict__ spw, int* __restrict__ ssw,
    float& accO, float& lO)
{
    float m = -1e30f;
    for (int e = beg + lane; e < end; e += 32) {
        int s = g_srcs[e];
        int fs = remap ? remap[s] : s;
        float lg = as_in[fs * HH + h] + adv;
        lg = lg > 0.f ? lg : 0.2f * lg;
        m = fmaxf(m, lg);
    }
    #pragma unroll
    for (int o = 16; o; o >>= 1) m = fmaxf(m, __shfl_xor_sync(0xffffffffu, m, o));

    float l = 0.f, acc = 0.f;
    for (int base = beg; base < end; base += 32) {
        int e = base + lane;
        int s = 0;
        float p = 0.f;
        if (e < end) {
            s = g_srcs[e];
            if (remap) s = remap[s];
            float lg = as_in[s * HH + h] + adv;
            lg = lg > 0.f ? lg : 0.2f * lg;
            p = __expf(lg - m);
        }
        l += p;
        spw[lane] = p;
        ssw[lane] = s;
        __syncwarp();
        int cnt = min(32, end - base);
        #pragma unroll 4
        for (int i = 0; i < cnt; i++) {
            acc += spw[i] * xp[(long)ssw[i] * HC + h * CC + lane];
        }
        __syncwarp();
    }
    #pragma unroll
    for (int o = 16; o; o >>= 1) l += __shfl_xor_sync(0xffffffffu, l, o);
    accO = acc; lO = l;
}

// ---------------- FUSED: aggregate1 -> smem h1 tile -> GEMM2 + alpha2 -------
// Reads layer-1 alphas from as_in/ad_in (g_as/g_ad); writes layer-2 alphas to
// DISTINCT buffers as_out/ad_out (g_as2/g_ad2) — no cross-CTA aliasing.
__global__ __launch_bounds__(256) void agg1_gemm2_kernel(
    const float* __restrict__ xp1, const float* __restrict__ as_in,
    const float* __restrict__ ad_in, const float* __restrict__ bias1,
    const float* __restrict__ W2,
    const float* __restrict__ a_src2, const float* __restrict__ a_dst2,
    float* __restrict__ xp2, float* __restrict__ as_out, float* __restrict__ ad_out)
{
    int fcnt = g_fcnt;
    int row0 = blockIdx.x * 128;
    if (row0 >= fcnt) return;

    extern __shared__ float dsm[];
    float (*Asm)[132] = (float (*)[132])dsm;                 // 128 x 132 (h1^T tile)
    float (*Bsm)[128] = (float (*)[128])(dsm + 128 * 132);   // 128 x 128 (W2)
    __shared__ float sp[8][32];
    __shared__ int   ss[8][32];

    int tid = threadIdx.x, wid = tid >> 5, lane = tid & 31;

    // phase 0: stage W2 (latency hidden under phase 1; consumed after sync)
    {
        const float4* src = (const float4*)W2;
        float4* dst = (float4*)Bsm;
        for (int i = tid; i < 4096; i += 256) dst[i] = src[i];
    }

    // phase 1: aggregate 128 frontier nodes into Asm[k][row]
    int grp = wid >> 2, h = wid & 3;
    float biasv = bias1[h * CC + lane];
    for (int i = grp; i < 128; i += 2) {
        int bi = row0 + i;
        float o = 0.f;
        if (bi < fcnt) {
            int node = g_flist[bi];
            int beg = g_rowptr[node], end = g_rowptr[node + 1];
            float adv = ad_in[node * HH + h];
            float acc, l;
            aggregate_node(xp1, as_in, adv, beg, end, h, lane, nullptr,
                           sp[wid], ss[wid], acc, l);
            o = fmaxf(acc / (l + 1e-16f) + biasv, 0.f);   // relu
        }
        Asm[h * CC + lane][i] = o;
    }
    __syncthreads();

    // phase 2: GEMM  xp2[row][n] = sum_k Asm[k][row] * Bsm[k][n]
    int tx = tid & 15, ty = tid >> 4;
    unsigned long long acc2[8][4];
    #pragma unroll
    for (int i = 0; i < 8; i++)
        #pragma unroll
        for (int j = 0; j < 4; j++) acc2[i][j] = 0ULL;

    for (int k = 0; k < 128; k++) {
        float4 a0 = *(const float4*)&Asm[k][ty * 8];
        float4 a1 = *(const float4*)&Asm[k][ty * 8 + 4];
        ulonglong2 bl = *(const ulonglong2*)&Bsm[k][tx * 8];
        ulonglong2 bh = *(const ulonglong2*)&Bsm[k][tx * 8 + 4];
        unsigned long long br2[4] = {bl.x, bl.y, bh.x, bh.y};
        float ar[8] = {a0.x, a0.y, a0.z, a0.w, a1.x, a1.y, a1.z, a1.w};
        unsigned long long ap[8];
        #pragma unroll
        for (int i = 0; i < 8; i++) SPLAT2(ap[i], ar[i]);
        #pragma unroll
        for (int i = 0; i < 8; i++)
            #pragma unroll
            for (int j = 0; j < 4; j++)
                FMA2(acc2[i][j], ap[i], br2[j]);
    }

    // epilogue: write xp2 + fused layer-2 alpha (to separate buffers)
    float4 av0 = *(const float4*)&a_src2[tx * 8];
    float4 av1 = *(const float4*)&a_src2[tx * 8 + 4];
    float4 dv0 = *(const float4*)&a_dst2[tx * 8];
    float4 dv1 = *(const float4*)&a_dst2[tx * 8 + 4];
    int hh = tx >> 2;

    #pragma unroll
    for (int i = 0; i < 8; i++) {
        float c[8];
        #pragma unroll
        for (int j = 0; j < 4; j++) {
            unsigned int lo, hi;
            UNPACK2(lo, hi, acc2[i][j]);
            c[2 * j]     = __uint_as_float(lo);
            c[2 * j + 1] = __uint_as_float(hi);
        }
        int gr = row0 + ty * 8 + i;
        bool valid = gr < fcnt;
        if (valid) {
            *(float4*)&xp2[(long)gr * 128 + tx * 8]     = make_float4(c[0], c[1], c[2], c[3]);
            *(float4*)&xp2[(long)gr * 128 + tx * 8 + 4] = make_float4(c[4], c[5], c[6], c[7]);
        }
        float s1 = c[0]*av0.x + c[1]*av0.y + c[2]*av0.z + c[3]*av0.w
                 + c[4]*av1.x + c[5]*av1.y + c[6]*av1.z + c[7]*av1.w;
        float s2 = c[0]*dv0.x + c[1]*dv0.y + c[2]*dv0.z + c[3]*dv0.w
                 + c[4]*dv1.x + c[5]*dv1.y + c[6]*dv1.z + c[7]*dv1.w;
        s1 += __shfl_xor_sync(0xffffffffu, s1, 1);
        s1 += __shfl_xor_sync(0xffffffffu, s1, 2);
        s2 += __shfl_xor_sync(0xffffffffu, s2, 1);
        s2 += __shfl_xor_sync(0xffffffffu, s2, 2);
        if (valid && (lane & 3) == 0) {
            as_out[gr * HH + hh] = s1;
            ad_out[gr * HH + hh] = s2;
        }
    }
}

// ---------------- layer-2 aggregation at root nodes ----------------
__global__ void aggregate2_kernel(const float* __restrict__ xpc,
                                  const float* __restrict__ as_c,
                                  const float* __restrict__ ad_c,
                                  const float* __restrict__ bias,
                                  float* __restrict__ out,
                                  const int* __restrict__ roots)
{
    __shared__ float sp[HH][32];
    __shared__ int   ss[HH][32];
    int bi   = blockIdx.x;
    int node = roots[bi];
    int tid  = threadIdx.x;
    int h = tid >> 5, lane = tid & 31;

    int beg = g_rowptr[node];
    int end = g_rowptr[node + 1];
    float adv = ad_c[g_finv[node] * HH + h];

    float acc, l;
    aggregate_node(xpc, as_c, adv, beg, end, h, lane, g_finv, sp[h], ss[h], acc, l);
    out[(long)bi * HC + tid] = acc / (l + 1e-16f) + bias[h * CC + lane];
}

// ---------------- launch ----------------
extern "C" void kernel_launch(void* const* d_in, const int* in_sizes, int n_in,
                              void* d_out, int out_size)
{
    const float* x    = (const float*)d_in[0];
    const int*   ei   = (const int*)  d_in[1];
    const int*   root = (const int*)  d_in[2];
    const float* W1   = (const float*)d_in[3];
    const float* as1  = (const float*)d_in[4];
    const float* ad1  = (const float*)d_in[5];
    const float* b1   = (const float*)d_in[6];
    const float* W2   = (const float*)d_in[7];
    const float* as2  = (const float*)d_in[8];
    const float* ad2  = (const float*)d_in[9];
    const float* b2   = (const float*)d_in[10];
    float* out = (float*)d_out;
    int n_roots = in_sizes[2];

    float *d_xp1, *d_xp2, *d_as, *d_ad, *d_as2, *d_ad2;
    cudaGetSymbolAddress((void**)&d_xp1, g_xp1);
    cudaGetSymbolAddress((void**)&d_xp2, g_xp2);
    cudaGetSymbolAddress((void**)&d_as,  g_as);
    cudaGetSymbolAddress((void**)&d_ad,  g_ad);
    cudaGetSymbolAddress((void**)&d_as2, g_as2);
    cudaGetSymbolAddress((void**)&d_ad2, g_ad2);

    // one-time setup (first, uncaptured call)
    static cudaStream_t s2 = nullptr;
    static cudaEvent_t evFork = nullptr, evJoin = nullptr;
    static bool attrs_set = false;
    const int SMEM_G1 = (2 * 16 * 256 + 2 * 16 * 128) * (int)sizeof(float);   // 49152
    const int SMEM_FU = (128 * 132 + 128 * 128) * (int)sizeof(float);         // 133120
    if (!s2) {
        cudaStreamCreateWithFlags(&s2, cudaStreamNonBlocking);
        cudaEventCreateWithFlags(&evFork, cudaEventDisableTiming);
        cudaEventCreateWithFlags(&evJoin, cudaEventDisableTiming);
    }
    if (!attrs_set) {
        cudaFuncSetAttribute(gemm_alpha_kernel<256>,
                             cudaFuncAttributeMaxDynamicSharedMemorySize, SMEM_G1);
        cudaFuncSetAttribute(agg1_gemm2_kernel,
                             cudaFuncAttributeMaxDynamicSharedMemorySize, SMEM_FU);
        attrs_set = true;
    }

    // ---- fork: CSR build + frontier on s2, concurrent with GEMM1 on stream 0
    cudaEventRecord(evFork, 0);
    cudaStreamWaitEvent(s2, evFork, 0);

    init_kernel<<<NB, 1024, 0, s2>>>();
    hist_kernel<<<(ET + 511) / 512, 512, 0, s2>>>(ei);
    scan1_kernel<<<NB, 1024, 0, s2>>>();
    scan3_kernel<<<NB, 1024, 0, s2>>>();
    scatter_kernel<<<(ET + 511) / 512, 512, 0, s2>>>(ei);
    mark_roots_kernel<<<n_roots, 32, 0, s2>>>(root);
    compact_kernel<<<(NN + 255) / 256, 256, 0, s2>>>();
    cudaEventRecord(evJoin, s2);

    // ---- stream 0: layer-1 GEMM (+fused alpha), independent of CSR
    gemm_alpha_kernel<256><<<GRID1, 256, SMEM_G1>>>(x, W1, d_xp1, as1, ad1, d_as, d_ad);

    // ---- join, then fused aggregate1+GEMM2+alpha2, then root aggregation
    cudaStreamWaitEvent(0, evJoin, 0);
    agg1_gemm2_kernel<<<GRID1, 256, SMEM_FU>>>(
        d_xp1, d_as, d_ad, b1, W2, as2, ad2, d_xp2, d_as2, d_ad2);
    aggregate2_kernel<<<n_roots, 128>>>(d_xp2, d_as2, d_ad2, b2, out, root);
}

// round 15
// speedup vs baseline: 1.7505x; 1.7505x over previous
#include <cuda_runtime.h>
#include <cuda_bf16.h>

#define NN 50000
#define EE 800000
#define ET (EE + NN)          // edges + self loops = 850000
#define HC 128                // H*C
#define HH 4
#define CC 32
#define NB 49                 // scan blocks: ceil(NN/1024)
#define GRID1 ((NN + 127) / 128)

// ---------------- device scratch (static, no allocation) ----------------
__device__ float g_xp1[NN * HC];     // layer1 linear out (full)
__device__ float g_h1 [NN * HC];     // layer1 final (COMPACTED frontier rows)
__device__ float g_xp2[NN * HC];     // layer2 linear out (COMPACTED)
__device__ float g_as [NN * HH];
__device__ float g_ad [NN * HH];
__device__ int   g_cnt[NN];          // degree histogram / scatter countdown
__device__ int   g_rowptr[NN + 1];
__device__ int   g_srcs[ET];         // CSR (by dst) source indices
__device__ int   g_mark[NN];
__device__ int   g_finv[NN];         // node -> compact frontier index
__device__ int   g_flist[NN];        // compact frontier index -> node
__device__ int   g_fcnt;
__device__ int   g_bsum[NB];

// ---------------- f32x2 helpers ----------------
#define FMA2(acc, a, b) asm("fma.rn.f32x2 %0, %1, %2, %0;" : "+l"(acc) : "l"(a), "l"(b))
#define SPLAT2(dst, s)  asm("mov.b64 %0, {%1, %1};" : "=l"(dst) : "r"(__float_as_uint(s)))
#define UNPACK2(lo, hi, p) asm("mov.b64 {%0, %1}, %2;" : "=r"(lo), "=r"(hi) : "l"(p))

// ---------------- init: zero cnt/mark/fcnt ----------------
__global__ void init_kernel() {
    int i = blockIdx.x * blockDim.x + threadIdx.x;
    if (i < NN) { g_cnt[i] = 0; g_mark[i] = 0; }
    if (i == 0) g_fcnt = 0;
}

__global__ void hist_kernel(const int* __restrict__ ei) {
    int e = blockIdx.x * blockDim.x + threadIdx.x;
    if (e >= ET) return;
    int d = (e < EE) ? ei[EE + e] : (e - EE);
    atomicAdd(&g_cnt[d], 1);
}

// ---------------- 2-phase scan ----------------
__global__ void scan1_kernel() {
    __shared__ int wsum[32];
    int tid = threadIdx.x, lane = tid & 31, w = tid >> 5;
    int i = blockIdx.x * 1024 + tid;
    int v = (i < NN) ? g_cnt[i] : 0;
    int x = v;
    #pragma unroll
    for (int o = 1; o < 32; o <<= 1) {
        int t = __shfl_up_sync(0xffffffffu, x, o);
        if (lane >= o) x += t;
    }
    if (lane == 31) wsum[w] = x;
    __syncthreads();
    if (w == 0) {
        int y = wsum[lane];
        #pragma unroll
        for (int o = 1; o < 32; o <<= 1) {
            int t = __shfl_up_sync(0xffffffffu, y, o);
            if (lane >= o) y += t;
        }
        wsum[lane] = y;
    }
    __syncthreads();
    int incl = x + (w > 0 ? wsum[w - 1] : 0);
    if (i < NN) g_rowptr[i + 1] = incl;
    if (tid == 1023) g_bsum[blockIdx.x] = incl;
    if (i == 0) g_rowptr[0] = 0;
}

__global__ void scan3_kernel() {
    __shared__ int s_off;
    int tid = threadIdx.x;
    if (tid < 32) {
        int v = 0;
        if (tid      < (int)blockIdx.x) v += g_bsum[tid];
        if (tid + 32 < (int)blockIdx.x) v += g_bsum[tid + 32];
        #pragma unroll
        for (int o = 16; o; o >>= 1) v += __shfl_xor_sync(0xffffffffu, v, o);
        if (tid == 0) s_off = v;
    }
    __syncthreads();
    int i = blockIdx.x * 1024 + tid;
    if (i < NN && blockIdx.x > 0) g_rowptr[i + 1] += s_off;
}

__global__ void scatter_kernel(const int* __restrict__ ei) {
    int e = blockIdx.x * blockDim.x + threadIdx.x;
    if (e >= ET) return;
    int s, d;
    if (e < EE) { s = ei[e]; d = ei[EE + e]; }
    else        { s = e - EE; d = s; }
    int r = atomicSub(&g_cnt[d], 1);
    g_srcs[g_rowptr[d] + r - 1] = s;
}

// ---------------- frontier ----------------
__global__ void mark_roots_kernel(const int* __restrict__ roots) {
    int r = roots[blockIdx.x];
    if (threadIdx.x == 0) g_mark[r] = 1;
    int beg = g_rowptr[r], end = g_rowptr[r + 1];
    for (int e = beg + threadIdx.x; e < end; e += 32)
        g_mark[g_srcs[e]] = 1;
}

__global__ void compact_kernel() {
    int i = blockIdx.x * blockDim.x + threadIdx.x;
    int lane = threadIdx.x & 31;
    bool active = (i < NN) && g_mark[i];
    unsigned mask = __ballot_sync(0xffffffffu, active);
    if (!mask) return;
    int leader = __ffs(mask) - 1;
    int base = 0;
    if (lane == leader) base = atomicAdd(&g_fcnt, __popc(mask));
    base = __shfl_sync(0xffffffffu, base, leader);
    if (active) {
        int pos = base + __popc(mask & ((1u << lane) - 1u));
        g_flist[pos] = i;
        g_finv[i] = pos;
    }
}

// ---------------- GEMM1 + fused alpha: A-duplicated smem, double-buffered ----
// C[M,128] = A[M,256] * B[256,128]; epilogue produces as/ad.
// dyn smem: As2[2][16][256] (duplicated pairs) + Bs[2][16][128]  (48 KB)
__global__ __launch_bounds__(256) void gemm1_alpha_kernel(
    const float* __restrict__ A, const float* __restrict__ B, float* __restrict__ Cmat,
    const float* __restrict__ a_src, const float* __restrict__ a_dst,
    float* __restrict__ as_out, float* __restrict__ ad_out)
{
    constexpr int K = 256, NC = K / 16;
    const int M = NN;
    int row0 = blockIdx.x * 128;

    extern __shared__ float dsm[];
    float (*As2)[16][256] = (float (*)[16][256])dsm;            // 8192 floats
    float (*Bs)[16][128]  = (float (*)[16][128])(dsm + 8192);   // 4096 floats

    int tid = threadIdx.x;
    int tx = tid & 15;
    int ty = tid >> 4;

    unsigned long long acc2[8][4];
    #pragma unroll
    for (int i = 0; i < 8; i++)
        #pragma unroll
        for (int j = 0; j < 4; j++) acc2[i][j] = 0ULL;

    int lr = tid >> 1;
    int lk = (tid & 1) * 8;
    int bk = tid >> 4;
    int bn = (tid & 15) * 8;

    int grow = row0 + lr;
    bool arow_ok = grow < M;
    const float* Arow = A + (long)grow * K + lk;
    const float* Bp   = B + bk * 128 + bn;

    float4 pa0, pa1, pb0, pb1;
    if (arow_ok) {
        pa0 = *(const float4*)(Arow);
        pa1 = *(const float4*)(Arow + 4);
    } else {
        pa0 = make_float4(0, 0, 0, 0); pa1 = pa0;
    }
    pb0 = *(const float4*)(Bp);
    pb1 = *(const float4*)(Bp + 4);
    {
        float av[8] = {pa0.x, pa0.y, pa0.z, pa0.w, pa1.x, pa1.y, pa1.z, pa1.w};
        #pragma unroll
        for (int j = 0; j < 8; j++)
            *(float2*)&As2[0][lk + j][2 * lr] = make_float2(av[j], av[j]);
        *(float4*)&Bs[0][bk][bn]     = pb0;
        *(float4*)&Bs[0][bk][bn + 4] = pb1;
    }
    __syncthreads();

    int buf = 0;
    #pragma unroll
    for (int c = 0; c < NC; c++) {
        if (c + 1 < NC) {
            if (arow_ok) {
                pa0 = *(const float4*)(Arow + (c + 1) * 16);
                pa1 = *(const float4*)(Arow + (c + 1) * 16 + 4);
            }
            pb0 = *(const float4*)(Bp + (c + 1) * 16 * 128);
            pb1 = *(const float4*)(Bp + (c + 1) * 16 * 128 + 4);
        }

        #pragma unroll
        for (int k = 0; k < 16; k++) {
            ulonglong2 a0 = *(const ulonglong2*)&As2[buf][k][ty * 16];
            ulonglong2 a1 = *(const ulonglong2*)&As2[buf][k][ty * 16 + 4];
            ulonglong2 a2 = *(const ulonglong2*)&As2[buf][k][ty * 16 + 8];
            ulonglong2 a3 = *(const ulonglong2*)&As2[buf][k][ty * 16 + 12];
            ulonglong2 bl = *(const ulonglong2*)&Bs[buf][k][tx * 8];
            ulonglong2 bh = *(const ulonglong2*)&Bs[buf][k][tx * 8 + 4];
            unsigned long long ap[8] = {a0.x, a0.y, a1.x, a1.y, a2.x, a2.y, a3.x, a3.y};
            unsigned long long br2[4] = {bl.x, bl.y, bh.x, bh.y};
            #pragma unroll
            for (int i = 0; i < 8; i++)
                #pragma unroll
                for (int j = 0; j < 4; j++)
                    FMA2(acc2[i][j], ap[i], br2[j]);
        }

        if (c + 1 < NC) {
            int nb = buf ^ 1;
            float av[8] = {pa0.x, pa0.y, pa0.z, pa0.w, pa1.x, pa1.y, pa1.z, pa1.w};
            #pragma unroll
            for (int j = 0; j < 8; j++)
                *(float2*)&As2[nb][lk + j][2 * lr] = make_float2(av[j], av[j]);
            *(float4*)&Bs[nb][bk][bn]     = pb0;
            *(float4*)&Bs[nb][bk][bn + 4] = pb1;
            __syncthreads();
            buf = nb;
        }
    }

    float4 av0 = *(const float4*)&a_src[tx * 8];
    float4 av1 = *(const float4*)&a_src[tx * 8 + 4];
    float4 dv0 = *(const float4*)&a_dst[tx * 8];
    float4 dv1 = *(const float4*)&a_dst[tx * 8 + 4];
    int lane = tid & 31;
    int h = tx >> 2;

    #pragma unroll
    for (int i = 0; i < 8; i++) {
        float c[8];
        #pragma unroll
        for (int j = 0; j < 4; j++) {
            unsigned int lo, hi;
            UNPACK2(lo, hi, acc2[i][j]);
            c[2 * j]     = __uint_as_float(lo);
            c[2 * j + 1] = __uint_as_float(hi);
        }
        int gr = row0 + ty * 8 + i;
        bool valid = gr < M;
        if (valid) {
            *(float4*)&Cmat[(long)gr * 128 + tx * 8]     = make_float4(c[0], c[1], c[2], c[3]);
            *(float4*)&Cmat[(long)gr * 128 + tx * 8 + 4] = make_float4(c[4], c[5], c[6], c[7]);
        }
        float s1 = c[0]*av0.x + c[1]*av0.y + c[2]*av0.z + c[3]*av0.w
                 + c[4]*av1.x + c[5]*av1.y + c[6]*av1.z + c[7]*av1.w;
        float s2 = c[0]*dv0.x + c[1]*dv0.y + c[2]*dv0.z + c[3]*dv0.w
                 + c[4]*dv1.x + c[5]*dv1.y + c[6]*dv1.z + c[7]*dv1.w;
        s1 += __shfl_xor_sync(0xffffffffu, s1, 1);
        s1 += __shfl_xor_sync(0xffffffffu, s1, 2);
        s2 += __shfl_xor_sync(0xffffffffu, s2, 1);
        s2 += __shfl_xor_sync(0xffffffffu, s2, 2);
        if (valid && (lane & 3) == 0) {
            as_out[gr * HH + h] = s1;
            ad_out[gr * HH + h] = s2;
        }
    }
}

// ---------------- GEMM2 + fused alpha (R11 kernel, static smem, FRONT) ------
__global__ __launch_bounds__(256) void gemm2_alpha_kernel(
    const float* __restrict__ A, const float* __restrict__ B, float* __restrict__ Cmat,
    const float* __restrict__ a_src, const float* __restrict__ a_dst,
    float* __restrict__ as_out, float* __restrict__ ad_out)
{
    constexpr int K = 128, NC = K / 16;
    int M = g_fcnt;
    int row0 = blockIdx.x * 128;
    if (row0 >= M) return;

    __shared__ __align__(16) float As[2][16][128];
    __shared__ __align__(16) float Bs[2][16][128];
    int tid = threadIdx.x;
    int tx = tid & 15;
    int ty = tid >> 4;

    unsigned long long acc2[8][4];
    #pragma unroll
    for (int i = 0; i < 8; i++)
        #pragma unroll
        for (int j = 0; j < 4; j++) acc2[i][j] = 0ULL;

    int lr = tid >> 1;
    int lk = (tid & 1) * 8;
    int bk = tid >> 4;
    int bn = (tid & 15) * 8;

    int grow = row0 + lr;
    bool arow_ok = grow < M;
    const float* Arow = A + (long)grow * K + lk;
    const float* Bp   = B + bk * 128 + bn;

    float4 pa0, pa1, pb0, pb1;
    if (arow_ok) {
        pa0 = *(const float4*)(Arow);
        pa1 = *(const float4*)(Arow + 4);
    } else {
        pa0 = make_float4(0, 0, 0, 0); pa1 = pa0;
    }
    pb0 = *(const float4*)(Bp);
    pb1 = *(const float4*)(Bp + 4);
    {
        As[0][lk + 0][lr] = pa0.x; As[0][lk + 1][lr] = pa0.y;
        As[0][lk + 2][lr] = pa0.z; As[0][lk + 3][lr] = pa0.w;
        As[0][lk + 4][lr] = pa1.x; As[0][lk + 5][lr] = pa1.y;
        As[0][lk + 6][lr] = pa1.z; As[0][lk + 7][lr] = pa1.w;
        *(float4*)&Bs[0][bk][bn]     = pb0;
        *(float4*)&Bs[0][bk][bn + 4] = pb1;
    }
    __syncthreads();

    int buf = 0;
    #pragma unroll
    for (int c = 0; c < NC; c++) {
        if (c + 1 < NC) {
            if (arow_ok) {
                pa0 = *(const float4*)(Arow + (c + 1) * 16);
                pa1 = *(const float4*)(Arow + (c + 1) * 16 + 4);
            }
            pb0 = *(const float4*)(Bp + (c + 1) * 16 * 128);
            pb1 = *(const float4*)(Bp + (c + 1) * 16 * 128 + 4);
        }

        #pragma unroll
        for (int k = 0; k < 16; k++) {
            float4 a0 = *(const float4*)&As[buf][k][ty * 8];
            float4 a1 = *(const float4*)&As[buf][k][ty * 8 + 4];
            ulonglong2 bl = *(const ulonglong2*)&Bs[buf][k][tx * 8];
            ulonglong2 bh = *(const ulonglong2*)&Bs[buf][k][tx * 8 + 4];
            unsigned long long br2[4] = {bl.x, bl.y, bh.x, bh.y};
            float ar[8] = {a0.x, a0.y, a0.z, a0.w, a1.x, a1.y, a1.z, a1.w};
            unsigned long long ap[8];
            #pragma unroll
            for (int i = 0; i < 8; i++) SPLAT2(ap[i], ar[i]);
            #pragma unroll
            for (int i = 0; i < 8; i++)
                #pragma unroll
                for (int j = 0; j < 4; j++)
                    FMA2(acc2[i][j], ap[i], br2[j]);
        }

        if (c + 1 < NC) {
            int nb = buf ^ 1;
            As[nb][lk + 0][lr] = pa0.x; As[nb][lk + 1][lr] = pa0.y;
            As[nb][lk + 2][lr] = pa0.z; As[nb][lk + 3][lr] = pa0.w;
            As[nb][lk + 4][lr] = pa1.x; As[nb][lk + 5][lr] = pa1.y;
            As[nb][lk + 6][lr] = pa1.z; As[nb][lk + 7][lr] = pa1.w;
            *(float4*)&Bs[nb][bk][bn]     = pb0;
            *(float4*)&Bs[nb][bk][bn + 4] = pb1;
            __syncthreads();
            buf = nb;
        }
    }

    float4 av0 = *(const float4*)&a_src[tx * 8];
    float4 av1 = *(const float4*)&a_src[tx * 8 + 4];
    float4 dv0 = *(const float4*)&a_dst[tx * 8];
    float4 dv1 = *(const float4*)&a_dst[tx * 8 + 4];
    int lane = tid & 31;
    int h = tx >> 2;

    #pragma unroll
    for (int i = 0; i < 8; i++) {
        float c[8];
        #pragma unroll
        for (int j = 0; j < 4; j++) {
            unsigned int lo, hi;
            UNPACK2(lo, hi, acc2[i][j]);
            c[2 * j]     = __uint_as_float(lo);
            c[2 * j + 1] = __uint_as_float(hi);
        }
        int gr = row0 + ty * 8 + i;
        bool valid = gr < M;
        if (valid) {
            *(float4*)&Cmat[(long)gr * 128 + tx * 8]     = make_float4(c[0], c[1], c[2], c[3]);
            *(float4*)&Cmat[(long)gr * 128 + tx * 8 + 4] = make_float4(c[4], c[5], c[6], c[7]);
        }
        float s1 = c[0]*av0.x + c[1]*av0.y + c[2]*av0.z + c[3]*av0.w
                 + c[4]*av1.x + c[5]*av1.y + c[6]*av1.z + c[7]*av1.w;
        float s2 = c[0]*dv0.x + c[1]*dv0.y + c[2]*dv0.z + c[3]*dv0.w
                 + c[4]*dv1.x + c[5]*dv1.y + c[6]*dv1.z + c[7]*dv1.w;
        s1 += __shfl_xor_sync(0xffffffffu, s1, 1);
        s1 += __shfl_xor_sync(0xffffffffu, s1, 2);
        s2 += __shfl_xor_sync(0xffffffffu, s2, 1);
        s2 += __shfl_xor_sync(0xffffffffu, s2, 2);
        if (valid && (lane & 3) == 0) {
            as_out[gr * HH + h] = s1;
            ad_out[gr * HH + h] = s2;
        }
    }
}

// ---------------- two-pass softmax aggregation core ----------------
__device__ __forceinline__ void aggregate_node(
    const float* __restrict__ xp, const float* __restrict__ as_in, float adv,
    int beg, int end, int h, int lane, const int* __restrict__ remap,
    float& accO, float& lO)
{
    __shared__ float sp[HH][32];
    __shared__ int   ss[HH][32];

    float m = -1e30f;
    for (int e = beg + lane; e < end; e += 32) {
        int s = g_srcs[e];
        int fs = remap ? remap[s] : s;
        float lg = as_in[fs * HH + h] + adv;
        lg = lg > 0.f ? lg : 0.2f * lg;
        m = fmaxf(m, lg);
    }
    #pragma unroll
    for (int o = 16; o; o >>= 1) m = fmaxf(m, __shfl_xor_sync(0xffffffffu, m, o));

    float l = 0.f, acc = 0.f;
    for (int base = beg; base < end; base += 32) {
        int e = base + lane;
        int s = 0;
        float p = 0.f;
        if (e < end) {
            s = g_srcs[e];
            if (remap) s = remap[s];
            float lg = as_in[s * HH + h] + adv;
            lg = lg > 0.f ? lg : 0.2f * lg;
            p = __expf(lg - m);
        }
        l += p;
        sp[h][lane] = p;
        ss[h][lane] = s;
        __syncwarp();
        int cnt = min(32, end - base);
        #pragma unroll 4
        for (int i = 0; i < cnt; i++) {
            acc += sp[h][i] * xp[(long)ss[h][i] * HC + h * CC + lane];
        }
        __syncwarp();
    }
    #pragma unroll
    for (int o = 16; o; o >>= 1) l += __shfl_xor_sync(0xffffffffu, l, o);
    accO = acc; lO = l;
}

// grid-stride over frontier nodes
__global__ void aggregate1_kernel(const float* __restrict__ xp,
                                  const float* __restrict__ as_in,
                                  const float* __restrict__ ad_in,
                                  const float* __restrict__ bias,
                                  float* __restrict__ out)
{
    int tid  = threadIdx.x;
    int h = tid >> 5, lane = tid & 31;
    for (int bi = blockIdx.x; bi < g_fcnt; bi += gridDim.x) {
        int node = g_flist[bi];
        int beg = g_rowptr[node];
        int end = g_rowptr[node + 1];
        float adv = ad_in[node * HH + h];

        float acc, l;
        aggregate_node(xp, as_in, adv, beg, end, h, lane, nullptr, acc, l);
        float o = acc / (l + 1e-16f) + bias[h * CC + lane];
        out[(long)bi * HC + tid] = fmaxf(o, 0.f);   // relu
        __syncthreads();
    }
}

__global__ void aggregate2_kernel(const float* __restrict__ xpc,
                                  const float* __restrict__ as_c,
                                  const float* __restrict__ ad_c,
                                  const float* __restrict__ bias,
                                  float* __restrict__ out,
                                  const int* __restrict__ roots)
{
    int bi   = blockIdx.x;
    int node = roots[bi];
    int tid  = threadIdx.x;
    int h = tid >> 5, lane = tid & 31;

    int beg = g_rowptr[node];
    int end = g_rowptr[node + 1];
    float adv = ad_c[g_finv[node] * HH + h];

    float acc, l;
    aggregate_node(xpc, as_c, adv, beg, end, h, lane, g_finv, acc, l);
    out[(long)bi * HC + tid] = acc / (l + 1e-16f) + bias[h * CC + lane];
}

// ---------------- launch ----------------
extern "C" void kernel_launch(void* const* d_in, const int* in_sizes, int n_in,
                              void* d_out, int out_size)
{
    const float* x    = (const float*)d_in[0];
    const int*   ei   = (const int*)  d_in[1];
    const int*   root = (const int*)  d_in[2];
    const float* W1   = (const float*)d_in[3];
    const float* as1  = (const float*)d_in[4];
    const float* ad1  = (const float*)d_in[5];
    const float* b1   = (const float*)d_in[6];
    const float* W2   = (const float*)d_in[7];
    const float* as2  = (const float*)d_in[8];
    const float* ad2  = (const float*)d_in[9];
    const float* b2   = (const float*)d_in[10];
    float* out = (float*)d_out;
    int n_roots = in_sizes[2];

    float *d_xp1, *d_h1, *d_xp2, *d_as, *d_ad;
    cudaGetSymbolAddress((void**)&d_xp1, g_xp1);
    cudaGetSymbolAddress((void**)&d_h1,  g_h1);
    cudaGetSymbolAddress((void**)&d_xp2, g_xp2);
    cudaGetSymbolAddress((void**)&d_as,  g_as);
    cudaGetSymbolAddress((void**)&d_ad,  g_ad);

    // one-time setup (first, uncaptured call)
    static cudaStream_t s2 = nullptr;
    static cudaEvent_t evFork = nullptr, evJoin = nullptr;
    static bool attrs_set = false;
    const int SMEM_G1 = (2 * 16 * 256 + 2 * 16 * 128) * (int)sizeof(float);   // 49152
    if (!s2) {
        cudaStreamCreateWithFlags(&s2, cudaStreamNonBlocking);
        cudaEventCreateWithFlags(&evFork, cudaEventDisableTiming);
        cudaEventCreateWithFlags(&evJoin, cudaEventDisableTiming);
    }
    if (!attrs_set) {
        cudaFuncSetAttribute(gemm1_alpha_kernel,
                             cudaFuncAttributeMaxDynamicSharedMemorySize, SMEM_G1);
        attrs_set = true;
    }

    // ---- fork: CSR build + frontier on s2, concurrent with GEMM1 on stream 0
    cudaEventRecord(evFork, 0);
    cudaStreamWaitEvent(s2, evFork, 0);

    init_kernel<<<NB, 1024, 0, s2>>>();
    hist_kernel<<<(ET + 511) / 512, 512, 0, s2>>>(ei);
    scan1_kernel<<<NB, 1024, 0, s2>>>();
    scan3_kernel<<<NB, 1024, 0, s2>>>();
    scatter_kernel<<<(ET + 511) / 512, 512, 0, s2>>>(ei);
    mark_roots_kernel<<<n_roots, 32, 0, s2>>>(root);
    compact_kernel<<<(NN + 255) / 256, 256, 0, s2>>>();
    cudaEventRecord(evJoin, s2);

    // ---- stream 0: layer-1 GEMM (+fused alpha), independent of CSR
    gemm1_alpha_kernel<<<GRID1, 256, SMEM_G1>>>(x, W1, d_xp1, as1, ad1, d_as, d_ad);

    // ---- join, then aggregation / layer 2
    cudaStreamWaitEvent(0, evJoin, 0);
    aggregate1_kernel<<<24576, 128>>>(d_xp1, d_as, d_ad, b1, d_h1);

    gemm2_alpha_kernel<<<GRID1, 256>>>(d_h1, W2, d_xp2, as2, ad2, d_as, d_ad);
    aggregate2_kernel<<<n_roots, 128>>>(d_xp2, d_as, d_ad, b2, out, root);
}

// round 16
// speedup vs baseline: 1.9214x; 1.0977x over previous
#include <cuda_runtime.h>
#include <cuda_bf16.h>

#define NN 50000
#define EE 800000
#define ET (EE + NN)          // edges + self loops = 850000
#define HC 128                // H*C
#define HH 4
#define CC 32
#define NB 49                 // scan blocks: ceil(NN/1024)
#define GRID1 ((NN + 127) / 128)

// ---------------- device scratch (static, no allocation) ----------------
__device__ float g_xp1[NN * HC];     // layer1 linear out (full)
__device__ float g_h1 [NN * HC];     // layer1 final (COMPACTED frontier rows)
__device__ float g_xp2[NN * HC];     // layer2 linear out (COMPACTED)
__device__ float g_as [NN * HH];
__device__ float g_ad [NN * HH];
__device__ int   g_cnt[NN];          // degree histogram / scatter countdown
__device__ int   g_rowptr[NN + 1];
__device__ int   g_srcs[ET];         // CSR (by dst) source indices
__device__ int   g_mark[NN];
__device__ int   g_finv[NN];         // node -> compact frontier index
__device__ int   g_flist[NN];        // compact frontier index -> node
__device__ int   g_fcnt;
__device__ int   g_bsum[NB];

// ---------------- f32x2 helpers ----------------
#define FMA2(acc, a, b) asm("fma.rn.f32x2 %0, %1, %2, %0;" : "+l"(acc) : "l"(a), "l"(b))
#define SPLAT2(dst, s)  asm("mov.b64 %0, {%1, %1};" : "=l"(dst) : "r"(__float_as_uint(s)))
#define UNPACK2(lo, hi, p) asm("mov.b64 {%0, %1}, %2;" : "=r"(lo), "=r"(hi) : "l"(p))

// ---------------- init: zero cnt/mark/fcnt ----------------
__global__ void init_kernel() {
    int i = blockIdx.x * blockDim.x + threadIdx.x;
    if (i < NN) { g_cnt[i] = 0; g_mark[i] = 0; }
    if (i == 0) g_fcnt = 0;
}

__global__ void hist_kernel(const int* __restrict__ ei) {
    int e = blockIdx.x * blockDim.x + threadIdx.x;
    if (e >= ET) return;
    int d = (e < EE) ? ei[EE + e] : (e - EE);
    atomicAdd(&g_cnt[d], 1);
}

// ---------------- 2-phase scan ----------------
__global__ void scan1_kernel() {
    __shared__ int wsum[32];
    int tid = threadIdx.x, lane = tid & 31, w = tid >> 5;
    int i = blockIdx.x * 1024 + tid;
    int v = (i < NN) ? g_cnt[i] : 0;
    int x = v;
    #pragma unroll
    for (int o = 1; o < 32; o <<= 1) {
        int t = __shfl_up_sync(0xffffffffu, x, o);
        if (lane >= o) x += t;
    }
    if (lane == 31) wsum[w] = x;
    __syncthreads();
    if (w == 0) {
        int y = wsum[lane];
        #pragma unroll
        for (int o = 1; o < 32; o <<= 1) {
            int t = __shfl_up_sync(0xffffffffu, y, o);
            if (lane >= o) y += t;
        }
        wsum[lane] = y;
    }
    __syncthreads();
    int incl = x + (w > 0 ? wsum[w - 1] : 0);
    if (i < NN) g_rowptr[i + 1] = incl;
    if (tid == 1023) g_bsum[blockIdx.x] = incl;
    if (i == 0) g_rowptr[0] = 0;
}

__global__ void scan3_kernel() {
    __shared__ int s_off;
    int tid = threadIdx.x;
    if (tid < 32) {
        int v = 0;
        if (tid      < (int)blockIdx.x) v += g_bsum[tid];
        if (tid + 32 < (int)blockIdx.x) v += g_bsum[tid + 32];
        #pragma unroll
        for (int o = 16; o; o >>= 1) v += __shfl_xor_sync(0xffffffffu, v, o);
        if (tid == 0) s_off = v;
    }
    __syncthreads();
    int i = blockIdx.x * 1024 + tid;
    if (i < NN && blockIdx.x > 0) g_rowptr[i + 1] += s_off;
}

__global__ void scatter_kernel(const int* __restrict__ ei) {
    int e = blockIdx.x * blockDim.x + threadIdx.x;
    if (e >= ET) return;
    int s, d;
    if (e < EE) { s = ei[e]; d = ei[EE + e]; }
    else        { s = e - EE; d = s; }
    int r = atomicSub(&g_cnt[d], 1);
    g_srcs[g_rowptr[d] + r - 1] = s;
}

// ---------------- frontier ----------------
__global__ void mark_roots_kernel(const int* __restrict__ roots) {
    int r = roots[blockIdx.x];
    if (threadIdx.x == 0) g_mark[r] = 1;
    int beg = g_rowptr[r], end = g_rowptr[r + 1];
    for (int e = beg + threadIdx.x; e < end; e += 32)
        g_mark[g_srcs[e]] = 1;
}

__global__ void compact_kernel() {
    int i = blockIdx.x * blockDim.x + threadIdx.x;
    int lane = threadIdx.x & 31;
    bool active = (i < NN) && g_mark[i];
    unsigned mask = __ballot_sync(0xffffffffu, active);
    if (!mask) return;
    int leader = __ffs(mask) - 1;
    int base = 0;
    if (lane == leader) base = atomicAdd(&g_fcnt, __popc(mask));
    base = __shfl_sync(0xffffffffu, base, leader);
    if (active) {
        int pos = base + __popc(mask & ((1u << lane) - 1u));
        g_flist[pos] = i;
        g_finv[i] = pos;
    }
}

// ---------------- fused GEMM + alpha, double-buffered smem (R11 kernel) ----
// C[M,128] = A[M,K] * B[K,128]; epilogue produces as/ad = <row_h, att_h>.
template <int K, bool FRONT>
__global__ __launch_bounds__(256) void gemm_alpha_kernel(
    const float* __restrict__ A, const float* __restrict__ B, float* __restrict__ Cmat,
    const float* __restrict__ a_src, const float* __restrict__ a_dst,
    float* __restrict__ as_out, float* __restrict__ ad_out)
{
    constexpr int NC = K / 16;
    int M = FRONT ? g_fcnt : NN;
    int row0 = blockIdx.x * 128;
    if (row0 >= M) return;

    __shared__ __align__(16) float As[2][16][128];
    __shared__ __align__(16) float Bs[2][16][128];
    int tid = threadIdx.x;
    int tx = tid & 15;       // col group: cols tx*8..tx*8+7
    int ty = tid >> 4;       // row group: rows ty*8..ty*8+7

    unsigned long long acc2[8][4];
    #pragma unroll
    for (int i = 0; i < 8; i++)
        #pragma unroll
        for (int j = 0; j < 4; j++) acc2[i][j] = 0ULL;

    int lr = tid >> 1;           // 0..127 row for A load
    int lk = (tid & 1) * 8;      // 0 or 8
    int bk = tid >> 4;           // 0..15 k-row for B load
    int bn = (tid & 15) * 8;     // col

    int grow = row0 + lr;
    bool arow_ok = grow < M;
    const float* Arow = A + (long)grow * K + lk;
    const float* Bp   = B + bk * 128 + bn;

    float4 pa0, pa1, pb0, pb1;
    if (arow_ok) {
        pa0 = *(const float4*)(Arow);
        pa1 = *(const float4*)(Arow + 4);
    } else {
        pa0 = make_float4(0, 0, 0, 0); pa1 = pa0;
    }
    pb0 = *(const float4*)(Bp);
    pb1 = *(const float4*)(Bp + 4);
    {
        As[0][lk + 0][lr] = pa0.x; As[0][lk + 1][lr] = pa0.y;
        As[0][lk + 2][lr] = pa0.z; As[0][lk + 3][lr] = pa0.w;
        As[0][lk + 4][lr] = pa1.x; As[0][lk + 5][lr] = pa1.y;
        As[0][lk + 6][lr] = pa1.z; As[0][lk + 7][lr] = pa1.w;
        *(float4*)&Bs[0][bk][bn]     = pb0;
        *(float4*)&Bs[0][bk][bn + 4] = pb1;
    }
    __syncthreads();

    int buf = 0;
    #pragma unroll
    for (int c = 0; c < NC; c++) {
        if (c + 1 < NC) {
            if (arow_ok) {
                pa0 = *(const float4*)(Arow + (c + 1) * 16);
                pa1 = *(const float4*)(Arow + (c + 1) * 16 + 4);
            }
            pb0 = *(const float4*)(Bp + (c + 1) * 16 * 128);
            pb1 = *(const float4*)(Bp + (c + 1) * 16 * 128 + 4);
        }

        #pragma unroll
        for (int k = 0; k < 16; k++) {
            float4 a0 = *(const float4*)&As[buf][k][ty * 8];
            float4 a1 = *(const float4*)&As[buf][k][ty * 8 + 4];
            ulonglong2 bl = *(const ulonglong2*)&Bs[buf][k][tx * 8];
            ulonglong2 bh = *(const ulonglong2*)&Bs[buf][k][tx * 8 + 4];
            unsigned long long br2[4] = {bl.x, bl.y, bh.x, bh.y};
            float ar[8] = {a0.x, a0.y, a0.z, a0.w, a1.x, a1.y, a1.z, a1.w};
            unsigned long long ap[8];
            #pragma unroll
            for (int i = 0; i < 8; i++) SPLAT2(ap[i], ar[i]);
            #pragma unroll
            for (int i = 0; i < 8; i++)
                #pragma unroll
                for (int j = 0; j < 4; j++)
                    FMA2(acc2[i][j], ap[i], br2[j]);
        }

        if (c + 1 < NC) {
            int nb = buf ^ 1;
            As[nb][lk + 0][lr] = pa0.x; As[nb][lk + 1][lr] = pa0.y;
            As[nb][lk + 2][lr] = pa0.z; As[nb][lk + 3][lr] = pa0.w;
            As[nb][lk + 4][lr] = pa1.x; As[nb][lk + 5][lr] = pa1.y;
            As[nb][lk + 6][lr] = pa1.z; As[nb][lk + 7][lr] = pa1.w;
            *(float4*)&Bs[nb][bk][bn]     = pb0;
            *(float4*)&Bs[nb][bk][bn + 4] = pb1;
            __syncthreads();
            buf = nb;
        }
    }

    // attention vectors for this thread's 8-col chunk (within head h = tx>>2)
    float4 av0 = *(const float4*)&a_src[tx * 8];
    float4 av1 = *(const float4*)&a_src[tx * 8 + 4];
    float4 dv0 = *(const float4*)&a_dst[tx * 8];
    float4 dv1 = *(const float4*)&a_dst[tx * 8 + 4];
    int lane = tid & 31;
    int h = tx >> 2;

    #pragma unroll
    for (int i = 0; i < 8; i++) {
        float c[8];
        #pragma unroll
        for (int j = 0; j < 4; j++) {
            unsigned int lo, hi;
            UNPACK2(lo, hi, acc2[i][j]);
            c[2 * j]     = __uint_as_float(lo);
            c[2 * j + 1] = __uint_as_float(hi);
        }
        int gr = row0 + ty * 8 + i;
        bool valid = gr < M;
        if (valid) {
            *(float4*)&Cmat[(long)gr * 128 + tx * 8]     = make_float4(c[0], c[1], c[2], c[3]);
            *(float4*)&Cmat[(long)gr * 128 + tx * 8 + 4] = make_float4(c[4], c[5], c[6], c[7]);
        }
        float s1 = c[0]*av0.x + c[1]*av0.y + c[2]*av0.z + c[3]*av0.w
                 + c[4]*av1.x + c[5]*av1.y + c[6]*av1.z + c[7]*av1.w;
        float s2 = c[0]*dv0.x + c[1]*dv0.y + c[2]*dv0.z + c[3]*dv0.w
                 + c[4]*dv1.x + c[5]*dv1.y + c[6]*dv1.z + c[7]*dv1.w;
        s1 += __shfl_xor_sync(0xffffffffu, s1, 1);
        s1 += __shfl_xor_sync(0xffffffffu, s1, 2);
        s2 += __shfl_xor_sync(0xffffffffu, s2, 1);
        s2 += __shfl_xor_sync(0xffffffffu, s2, 2);
        if (valid && (lane & 3) == 0) {
            as_out[gr * HH + h] = s1;
            ad_out[gr * HH + h] = s2;
        }
    }
}

// ---------------- two-pass softmax aggregation core ----------------
// deg<=32 fast path: single gather, logits kept in registers (no second pass).
__device__ __forceinline__ void aggregate_node(
    const float* __restrict__ xp, const float* __restrict__ as_in, float adv,
    int beg, int end, int h, int lane, const int* __restrict__ remap,
    float& accO, float& lO)
{
    __shared__ float sp[HH][32];
    __shared__ int   ss[HH][32];

    int deg = end - beg;

    if (deg <= 32) {
        // ---- fast path: one batch, one gather of as_in ----
        int e = beg + lane;
        int s = 0;
        float lg = -1e30f;
        if (lane < deg) {
            s = g_srcs[e];
            if (remap) s = remap[s];
            lg = as_in[s * HH + h] + adv;
            lg = lg > 0.f ? lg : 0.2f * lg;
        }
        float m = lg;
        #pragma unroll
        for (int o = 16; o; o >>= 1) m = fmaxf(m, __shfl_xor_sync(0xffffffffu, m, o));

        float p = (lane < deg) ? __expf(lg - m) : 0.f;
        float l = p;
        sp[h][lane] = p;
        ss[h][lane] = s;
        __syncwarp();
        float acc = 0.f;
        #pragma unroll 4
        for (int i = 0; i < deg; i++) {
            acc += sp[h][i] * xp[(long)ss[h][i] * HC + h * CC + lane];
        }
        __syncwarp();
        #pragma unroll
        for (int o = 16; o; o >>= 1) l += __shfl_xor_sync(0xffffffffu, l, o);
        accO = acc; lO = l;
        return;
    }

    // ---- general path: two passes ----
    float m = -1e30f;
    for (int e = beg + lane; e < end; e += 32) {
        int s = g_srcs[e];
        int fs = remap ? remap[s] : s;
        float lg = as_in[fs * HH + h] + adv;
        lg = lg > 0.f ? lg : 0.2f * lg;
        m = fmaxf(m, lg);
    }
    #pragma unroll
    for (int o = 16; o; o >>= 1) m = fmaxf(m, __shfl_xor_sync(0xffffffffu, m, o));

    float l = 0.f, acc = 0.f;
    for (int base = beg; base < end; base += 32) {
        int e = base + lane;
        int s = 0;
        float p = 0.f;
        if (e < end) {
            s = g_srcs[e];
            if (remap) s = remap[s];
            float lg = as_in[s * HH + h] + adv;
            lg = lg > 0.f ? lg : 0.2f * lg;
            p = __expf(lg - m);
        }
        l += p;
        sp[h][lane] = p;
        ss[h][lane] = s;
        __syncwarp();
        int cnt = min(32, end - base);
        #pragma unroll 4
        for (int i = 0; i < cnt; i++) {
            acc += sp[h][i] * xp[(long)ss[h][i] * HC + h * CC + lane];
        }
        __syncwarp();
    }
    #pragma unroll
    for (int o = 16; o; o >>= 1) l += __shfl_xor_sync(0xffffffffu, l, o);
    accO = acc; lO = l;
}

// grid-stride over frontier nodes (no block barrier needed: smem is per-warp)
__global__ void aggregate1_kernel(const float* __restrict__ xp,
                                  const float* __restrict__ as_in,
                                  const float* __restrict__ ad_in,
                                  const float* __restrict__ bias,
                                  float* __restrict__ out)
{
    int tid  = threadIdx.x;
    int h = tid >> 5, lane = tid & 31;
    float biasv = bias[h * CC + lane];
    for (int bi = blockIdx.x; bi < g_fcnt; bi += gridDim.x) {
        int node = g_flist[bi];
        int beg = g_rowptr[node];
        int end = g_rowptr[node + 1];
        float adv = ad_in[node * HH + h];

        float acc, l;
        aggregate_node(xp, as_in, adv, beg, end, h, lane, nullptr, acc, l);
        float o = acc / (l + 1e-16f) + biasv;
        out[(long)bi * HC + tid] = fmaxf(o, 0.f);   // relu
    }
}

__global__ void aggregate2_kernel(const float* __restrict__ xpc,
                                  const float* __restrict__ as_c,
                                  const float* __restrict__ ad_c,
                                  const float* __restrict__ bias,
                                  float* __restrict__ out,
                                  const int* __restrict__ roots)
{
    int bi   = blockIdx.x;
    int node = roots[bi];
    int tid  = threadIdx.x;
    int h = tid >> 5, lane = tid & 31;

    int beg = g_rowptr[node];
    int end = g_rowptr[node + 1];
    float adv = ad_c[g_finv[node] * HH + h];

    float acc, l;
    aggregate_node(xpc, as_c, adv, beg, end, h, lane, g_finv, acc, l);
    out[(long)bi * HC + tid] = acc / (l + 1e-16f) + bias[h * CC + lane];
}

// ---------------- launch ----------------
extern "C" void kernel_launch(void* const* d_in, const int* in_sizes, int n_in,
                              void* d_out, int out_size)
{
    const float* x    = (const float*)d_in[0];
    const int*   ei   = (const int*)  d_in[1];
    const int*   root = (const int*)  d_in[2];
    const float* W1   = (const float*)d_in[3];
    const float* as1  = (const float*)d_in[4];
    const float* ad1  = (const float*)d_in[5];
    const float* b1   = (const float*)d_in[6];
    const float* W2   = (const float*)d_in[7];
    const float* as2  = (const float*)d_in[8];
    const float* ad2  = (const float*)d_in[9];
    const float* b2   = (const float*)d_in[10];
    float* out = (float*)d_out;
    int n_roots = in_sizes[2];

    float *d_xp1, *d_h1, *d_xp2, *d_as, *d_ad;
    cudaGetSymbolAddress((void**)&d_xp1, g_xp1);
    cudaGetSymbolAddress((void**)&d_h1,  g_h1);
    cudaGetSymbolAddress((void**)&d_xp2, g_xp2);
    cudaGetSymbolAddress((void**)&d_as,  g_as);
    cudaGetSymbolAddress((void**)&d_ad,  g_ad);

    // side stream + events, created once on the first (uncaptured) call
    static cudaStream_t s2 = nullptr;
    static cudaEvent_t evFork = nullptr, evJoin = nullptr;
    if (!s2) {
        cudaStreamCreateWithFlags(&s2, cudaStreamNonBlocking);
        cudaEventCreateWithFlags(&evFork, cudaEventDisableTiming);
        cudaEventCreateWithFlags(&evJoin, cudaEventDisableTiming);
    }

    // ---- fork: CSR build + frontier on s2, concurrent with GEMM1 on stream 0
    cudaEventRecord(evFork, 0);
    cudaStreamWaitEvent(s2, evFork, 0);

    init_kernel<<<NB, 1024, 0, s2>>>();
    hist_kernel<<<(ET + 511) / 512, 512, 0, s2>>>(ei);
    scan1_kernel<<<NB, 1024, 0, s2>>>();
    scan3_kernel<<<NB, 1024, 0, s2>>>();
    scatter_kernel<<<(ET + 511) / 512, 512, 0, s2>>>(ei);
    mark_roots_kernel<<<n_roots, 32, 0, s2>>>(root);
    compact_kernel<<<(NN + 255) / 256, 256, 0, s2>>>();
    cudaEventRecord(evJoin, s2);

    // ---- stream 0: layer-1 GEMM (+fused alpha), independent of CSR
    gemm_alpha_kernel<256, false><<<GRID1, 256>>>(x, W1, d_xp1, as1, ad1, d_as, d_ad);

    // ---- join, then aggregation / layer 2
    cudaStreamWaitEvent(0, evJoin, 0);
    aggregate1_kernel<<<24576, 128>>>(d_xp1, d_as, d_ad, b1, d_h1);

    gemm_alpha_kernel<128, true><<<GRID1, 256>>>(d_h1, W2, d_xp2, as2, ad2, d_as, d_ad);
    aggregate2_kernel<<<n_roots, 128>>>(d_xp2, d_as, d_ad, b2, out, root);
}

// round 17
// speedup vs baseline: 2.1918x; 1.1407x over previous
#include <cuda_runtime.h>
#include <cuda_bf16.h>

#define NN 50000
#define EE 800000
#define ET (EE + NN)          // edges + self loops = 850000
#define HC 128                // H*C
#define HH 4
#define CC 32
#define NB 49                 // scan blocks: ceil(NN/1024)
#define GRID1 ((NN + 127) / 128)

// ---------------- device scratch (static, no allocation) ----------------
__device__ float g_xp1[NN * HC];     // layer1 linear out (full)
__device__ float g_h1 [NN * HC];     // layer1 final (COMPACTED frontier rows)
__device__ float g_xp2[NN * HC];     // layer2 linear out (COMPACTED)
__device__ float g_as [NN * HH];
__device__ float g_ad [NN * HH];
__device__ int   g_cnt[NN];          // degree histogram / scatter countdown
__device__ int   g_rowptr[NN + 1];
__device__ int   g_srcs[ET];         // CSR (by dst) source indices
__device__ int   g_mark[NN];
__device__ int   g_finv[NN];         // node -> compact frontier index
__device__ int   g_flist[NN];        // compact frontier index -> node
__device__ int   g_fcnt;
__device__ int   g_bsum[NB];

// ---------------- f32x2 helpers ----------------
#define FMA2(acc, a, b) asm("fma.rn.f32x2 %0, %1, %2, %0;" : "+l"(acc) : "l"(a), "l"(b))
#define SPLAT2(dst, s)  asm("mov.b64 %0, {%1, %1};" : "=l"(dst) : "r"(__float_as_uint(s)))
#define UNPACK2(lo, hi, p) asm("mov.b64 {%0, %1}, %2;" : "=r"(lo), "=r"(hi) : "l"(p))

// ---------------- init: zero cnt/mark/fcnt ----------------
__global__ void init_kernel() {
    int i = blockIdx.x * blockDim.x + threadIdx.x;
    if (i < NN) { g_cnt[i] = 0; g_mark[i] = 0; }
    if (i == 0) g_fcnt = 0;
}

__global__ void hist_kernel(const int* __restrict__ ei) {
    int e = blockIdx.x * blockDim.x + threadIdx.x;
    if (e >= ET) return;
    int d = (e < EE) ? ei[EE + e] : (e - EE);
    atomicAdd(&g_cnt[d], 1);
}

// ---------------- 2-phase scan ----------------
__global__ void scan1_kernel() {
    __shared__ int wsum[32];
    int tid = threadIdx.x, lane = tid & 31, w = tid >> 5;
    int i = blockIdx.x * 1024 + tid;
    int v = (i < NN) ? g_cnt[i] : 0;
    int x = v;
    #pragma unroll
    for (int o = 1; o < 32; o <<= 1) {
        int t = __shfl_up_sync(0xffffffffu, x, o);
        if (lane >= o) x += t;
    }
    if (lane == 31) wsum[w] = x;
    __syncthreads();
    if (w == 0) {
        int y = wsum[lane];
        #pragma unroll
        for (int o = 1; o < 32; o <<= 1) {
            int t = __shfl_up_sync(0xffffffffu, y, o);
            if (lane >= o) y += t;
        }
        wsum[lane] = y;
    }
    __syncthreads();
    int incl = x + (w > 0 ? wsum[w - 1] : 0);
    if (i < NN) g_rowptr[i + 1] = incl;
    if (tid == 1023) g_bsum[blockIdx.x] = incl;
    if (i == 0) g_rowptr[0] = 0;
}

__global__ void scan3_kernel() {
    __shared__ int s_off;
    int tid = threadIdx.x;
    if (tid < 32) {
        int v = 0;
        if (tid      < (int)blockIdx.x) v += g_bsum[tid];
        if (tid + 32 < (int)blockIdx.x) v += g_bsum[tid + 32];
        #pragma unroll
        for (int o = 16; o; o >>= 1) v += __shfl_xor_sync(0xffffffffu, v, o);
        if (tid == 0) s_off = v;
    }
    __syncthreads();
    int i = blockIdx.x * 1024 + tid;
    if (i < NN && blockIdx.x > 0) g_rowptr[i + 1] += s_off;
}

__global__ void scatter_kernel(const int* __restrict__ ei) {
    int e = blockIdx.x * blockDim.x + threadIdx.x;
    if (e >= ET) return;
    int s, d;
    if (e < EE) { s = ei[e]; d = ei[EE + e]; }
    else        { s = e - EE; d = s; }
    int r = atomicSub(&g_cnt[d], 1);
    g_srcs[g_rowptr[d] + r - 1] = s;
}

// ---------------- frontier ----------------
__global__ void mark_roots_kernel(const int* __restrict__ roots) {
    int r = roots[blockIdx.x];
    if (threadIdx.x == 0) g_mark[r] = 1;
    int beg = g_rowptr[r], end = g_rowptr[r + 1];
    for (int e = beg + threadIdx.x; e < end; e += 32)
        g_mark[g_srcs[e]] = 1;
}

__global__ void compact_kernel() {
    int i = blockIdx.x * blockDim.x + threadIdx.x;
    int lane = threadIdx.x & 31;
    bool active = (i < NN) && g_mark[i];
    unsigned mask = __ballot_sync(0xffffffffu, active);
    if (!mask) return;
    int leader = __ffs(mask) - 1;
    int base = 0;
    if (lane == leader) base = atomicAdd(&g_fcnt, __popc(mask));
    base = __shfl_sync(0xffffffffu, base, leader);
    if (active) {
        int pos = base + __popc(mask & ((1u << lane) - 1u));
        g_flist[pos] = i;
        g_finv[i] = pos;
    }
}

// ---------------- fused GEMM + alpha: 512 threads, 8x4 thread tile ----------
// C[M,128] = A[M,K] * B[K,128]; epilogue produces as/ad = <row_h, att_h>.
// 16 warps (4/SMSP) for latency hiding; acc regs halved vs 8x8 tile.
template <int K, bool FRONT>
__global__ __launch_bounds__(512) void gemm_alpha_kernel(
    const float* __restrict__ A, const float* __restrict__ B, float* __restrict__ Cmat,
    const float* __restrict__ a_src, const float* __restrict__ a_dst,
    float* __restrict__ as_out, float* __restrict__ ad_out)
{
    constexpr int NC = K / 16;
    int M = FRONT ? g_fcnt : NN;
    int row0 = blockIdx.x * 128;
    if (row0 >= M) return;

    __shared__ __align__(16) float As[2][16][128];
    __shared__ __align__(16) float Bs[2][16][128];
    int tid = threadIdx.x;
    int tx = tid & 31;       // col group: cols tx*4..tx*4+3
    int ty = tid >> 5;       // row group (= warp id): rows ty*8..ty*8+7

    unsigned long long acc2[8][2];
    #pragma unroll
    for (int i = 0; i < 8; i++) { acc2[i][0] = 0ULL; acc2[i][1] = 0ULL; }

    int lr = tid >> 2;           // 0..127 row for A load
    int lk = (tid & 3) * 4;      // 0,4,8,12
    int bk = tid >> 5;           // 0..15 k-row for B load
    int bn = (tid & 31) * 4;     // col

    int grow = row0 + lr;
    bool arow_ok = grow < M;
    const float* Arow = A + (long)grow * K + lk;
    const float* Bp   = B + bk * 128 + bn;

    float4 pa, pb;
    if (arow_ok) pa = *(const float4*)(Arow);
    else         pa = make_float4(0, 0, 0, 0);
    pb = *(const float4*)(Bp);
    {
        As[0][lk + 0][lr] = pa.x; As[0][lk + 1][lr] = pa.y;
        As[0][lk + 2][lr] = pa.z; As[0][lk + 3][lr] = pa.w;
        *(float4*)&Bs[0][bk][bn] = pb;
    }
    __syncthreads();

    int buf = 0;
    #pragma unroll
    for (int c = 0; c < NC; c++) {
        if (c + 1 < NC) {
            if (arow_ok) pa = *(const float4*)(Arow + (c + 1) * 16);
            pb = *(const float4*)(Bp + (c + 1) * 16 * 128);
        }

        #pragma unroll
        for (int k = 0; k < 16; k++) {
            float4 a0 = *(const float4*)&As[buf][k][ty * 8];
            float4 a1 = *(const float4*)&As[buf][k][ty * 8 + 4];
            ulonglong2 bl = *(const ulonglong2*)&Bs[buf][k][tx * 4];
            unsigned long long br2[2] = {bl.x, bl.y};
            float ar[8] = {a0.x, a0.y, a0.z, a0.w, a1.x, a1.y, a1.z, a1.w};
            unsigned long long ap[8];
            #pragma unroll
            for (int i = 0; i < 8; i++) SPLAT2(ap[i], ar[i]);
            #pragma unroll
            for (int i = 0; i < 8; i++) {
                FMA2(acc2[i][0], ap[i], br2[0]);
                FMA2(acc2[i][1], ap[i], br2[1]);
            }
        }

        if (c + 1 < NC) {
            int nb = buf ^ 1;
            As[nb][lk + 0][lr] = pa.x; As[nb][lk + 1][lr] = pa.y;
            As[nb][lk + 2][lr] = pa.z; As[nb][lk + 3][lr] = pa.w;
            *(float4*)&Bs[nb][bk][bn] = pb;
            __syncthreads();
            buf = nb;
        }
    }

    // attention vectors for this thread's 4-col chunk (within head h = tx>>3)
    float4 av = *(const float4*)&a_src[tx * 4];
    float4 dv = *(const float4*)&a_dst[tx * 4];
    int lane = tid & 31;     // == tx
    int h = tx >> 3;

    #pragma unroll
    for (int i = 0; i < 8; i++) {
        float c[4];
        {
            unsigned int lo, hi;
            UNPACK2(lo, hi, acc2[i][0]);
            c[0] = __uint_as_float(lo); c[1] = __uint_as_float(hi);
            UNPACK2(lo, hi, acc2[i][1]);
            c[2] = __uint_as_float(lo); c[3] = __uint_as_float(hi);
        }
        int gr = row0 + ty * 8 + i;
        bool valid = gr < M;
        if (valid)
            *(float4*)&Cmat[(long)gr * 128 + tx * 4] = make_float4(c[0], c[1], c[2], c[3]);
        float s1 = c[0]*av.x + c[1]*av.y + c[2]*av.z + c[3]*av.w;
        float s2 = c[0]*dv.x + c[1]*dv.y + c[2]*dv.z + c[3]*dv.w;
        s1 += __shfl_xor_sync(0xffffffffu, s1, 1);
        s1 += __shfl_xor_sync(0xffffffffu, s1, 2);
        s1 += __shfl_xor_sync(0xffffffffu, s1, 4);
        s2 += __shfl_xor_sync(0xffffffffu, s2, 1);
        s2 += __shfl_xor_sync(0xffffffffu, s2, 2);
        s2 += __shfl_xor_sync(0xffffffffu, s2, 4);
        if (valid && (lane & 7) == 0) {
            as_out[gr * HH + h] = s1;
            ad_out[gr * HH + h] = s2;
        }
    }
}

// ---------------- two-pass softmax aggregation core ----------------
// deg<=32 fast path: single gather, logits kept in registers (no second pass).
__device__ __forceinline__ void aggregate_node(
    const float* __restrict__ xp, const float* __restrict__ as_in, float adv,
    int beg, int end, int h, int lane, const int* __restrict__ remap,
    float& accO, float& lO)
{
    __shared__ float sp[HH][32];
    __shared__ int   ss[HH][32];

    int deg = end - beg;

    if (deg <= 32) {
        int e = beg + lane;
        int s = 0;
        float lg = -1e30f;
        if (lane < deg) {
            s = g_srcs[e];
            if (remap) s = remap[s];
            lg = as_in[s * HH + h] + adv;
            lg = lg > 0.f ? lg : 0.2f * lg;
        }
        float m = lg;
        #pragma unroll
        for (int o = 16; o; o >>= 1) m = fmaxf(m, __shfl_xor_sync(0xffffffffu, m, o));

        float p = (lane < deg) ? __expf(lg - m) : 0.f;
        float l = p;
        sp[h][lane] = p;
        ss[h][lane] = s;
        __syncwarp();
        float acc = 0.f;
        #pragma unroll 4
        for (int i = 0; i < deg; i++) {
            acc += sp[h][i] * xp[(long)ss[h][i] * HC + h * CC + lane];
        }
        __syncwarp();
        #pragma unroll
        for (int o = 16; o; o >>= 1) l += __shfl_xor_sync(0xffffffffu, l, o);
        accO = acc; lO = l;
        return;
    }

    float m = -1e30f;
    for (int e = beg + lane; e < end; e += 32) {
        int s = g_srcs[e];
        int fs = remap ? remap[s] : s;
        float lg = as_in[fs * HH + h] + adv;
        lg = lg > 0.f ? lg : 0.2f * lg;
        m = fmaxf(m, lg);
    }
    #pragma unroll
    for (int o = 16; o; o >>= 1) m = fmaxf(m, __shfl_xor_sync(0xffffffffu, m, o));

    float l = 0.f, acc = 0.f;
    for (int base = beg; base < end; base += 32) {
        int e = base + lane;
        int s = 0;
        float p = 0.f;
        if (e < end) {
            s = g_srcs[e];
            if (remap) s = remap[s];
            float lg = as_in[s * HH + h] + adv;
            lg = lg > 0.f ? lg : 0.2f * lg;
            p = __expf(lg - m);
        }
        l += p;
        sp[h][lane] = p;
        ss[h][lane] = s;
        __syncwarp();
        int cnt = min(32, end - base);
        #pragma unroll 4
        for (int i = 0; i < cnt; i++) {
            acc += sp[h][i] * xp[(long)ss[h][i] * HC + h * CC + lane];
        }
        __syncwarp();
    }
    #pragma unroll
    for (int o = 16; o; o >>= 1) l += __shfl_xor_sync(0xffffffffu, l, o);
    accO = acc; lO = l;
}

// grid-stride over frontier nodes (no block barrier needed: smem is per-warp)
__global__ void aggregate1_kernel(const float* __restrict__ xp,
                                  const float* __restrict__ as_in,
                                  const float* __restrict__ ad_in,
                                  const float* __restrict__ bias,
                                  float* __restrict__ out)
{
    int tid  = threadIdx.x;
    int h = tid >> 5, lane = tid & 31;
    float biasv = bias[h * CC + lane];
    for (int bi = blockIdx.x; bi < g_fcnt; bi += gridDim.x) {
        int node = g_flist[bi];
        int beg = g_rowptr[node];
        int end = g_rowptr[node + 1];
        float adv = ad_in[node * HH + h];

        float acc, l;
        aggregate_node(xp, as_in, adv, beg, end, h, lane, nullptr, acc, l);
        float o = acc / (l + 1e-16f) + biasv;
        out[(long)bi * HC + tid] = fmaxf(o, 0.f);   // relu
    }
}

__global__ void aggregate2_kernel(const float* __restrict__ xpc,
                                  const float* __restrict__ as_c,
                                  const float* __restrict__ ad_c,
                                  const float* __restrict__ bias,
                                  float* __restrict__ out,
                                  const int* __restrict__ roots)
{
    int bi   = blockIdx.x;
    int node = roots[bi];
    int tid  = threadIdx.x;
    int h = tid >> 5, lane = tid & 31;

    int beg = g_rowptr[node];
    int end = g_rowptr[node + 1];
    float adv = ad_c[g_finv[node] * HH + h];

    float acc, l;
    aggregate_node(xpc, as_c, adv, beg, end, h, lane, g_finv, acc, l);
    out[(long)bi * HC + tid] = acc / (l + 1e-16f) + bias[h * CC + lane];
}

// ---------------- launch ----------------
extern "C" void kernel_launch(void* const* d_in, const int* in_sizes, int n_in,
                              void* d_out, int out_size)
{
    const float* x    = (const float*)d_in[0];
    const int*   ei   = (const int*)  d_in[1];
    const int*   root = (const int*)  d_in[2];
    const float* W1   = (const float*)d_in[3];
    const float* as1  = (const float*)d_in[4];
    const float* ad1  = (const float*)d_in[5];
    const float* b1   = (const float*)d_in[6];
    const float* W2   = (const float*)d_in[7];
    const float* as2  = (const float*)d_in[8];
    const float* ad2  = (const float*)d_in[9];
    const float* b2   = (const float*)d_in[10];
    float* out = (float*)d_out;
    int n_roots = in_sizes[2];

    float *d_xp1, *d_h1, *d_xp2, *d_as, *d_ad;
    cudaGetSymbolAddress((void**)&d_xp1, g_xp1);
    cudaGetSymbolAddress((void**)&d_h1,  g_h1);
    cudaGetSymbolAddress((void**)&d_xp2, g_xp2);
    cudaGetSymbolAddress((void**)&d_as,  g_as);
    cudaGetSymbolAddress((void**)&d_ad,  g_ad);

    // side stream + events, created once on the first (uncaptured) call
    static cudaStream_t s2 = nullptr;
    static cudaEvent_t evFork = nullptr, evJoin = nullptr;
    if (!s2) {
        cudaStreamCreateWithFlags(&s2, cudaStreamNonBlocking);
        cudaEventCreateWithFlags(&evFork, cudaEventDisableTiming);
        cudaEventCreateWithFlags(&evJoin, cudaEventDisableTiming);
    }

    // ---- fork: CSR build + frontier on s2, concurrent with GEMM1 on stream 0
    cudaEventRecord(evFork, 0);
    cudaStreamWaitEvent(s2, evFork, 0);

    init_kernel<<<NB, 1024, 0, s2>>>();
    hist_kernel<<<(ET + 511) / 512, 512, 0, s2>>>(ei);
    scan1_kernel<<<NB, 1024, 0, s2>>>();
    scan3_kernel<<<NB, 1024, 0, s2>>>();
    scatter_kernel<<<(ET + 511) / 512, 512, 0, s2>>>(ei);

    // ---- stream 0: layer-1 GEMM is the 6th launch (ncu -s 5 captures it)
    gemm_alpha_kernel<256, false><<<GRID1, 512>>>(x, W1, d_xp1, as1, ad1, d_as, d_ad);

    // ---- rest of frontier chain on s2 (stream-ordered after scatter)
    mark_roots_kernel<<<n_roots, 32, 0, s2>>>(root);
    compact_kernel<<<(NN + 255) / 256, 256, 0, s2>>>();
    cudaEventRecord(evJoin, s2);

    // ---- join, then aggregation / layer 2
    cudaStreamWaitEvent(0, evJoin, 0);
    aggregate1_kernel<<<24576, 128>>>(d_xp1, d_as, d_ad, b1, d_h1);

    gemm_alpha_kernel<128, true><<<GRID1, 512>>>(d_h1, W2, d_xp2, as2, ad2, d_as, d_ad);
    aggregate2_kernel<<<n_roots, 128>>>(d_xp2, d_as, d_ad, b2, out, root);
}